// round 13
// baseline (speedup 1.0000x reference)
#include <cuda_runtime.h>
#include <cuda_bf16.h>

// Two kernels. result(row) = sum over 28 chunk-pair tables T_(A,B)[nA][nB]
// (32 bits -> 8 nibbles; all 528 order<=2 terms folded into tables).
// Precompute builds g_tab once (28 blocks). Eval stages rows via a 3-deep
// cp.async ring (XOR-swizzled), tables via cp.async too; 4 tiles per block.

#define NPAIRS 28
#define TABSZ (NPAIRS * 256)        // 7168 floats = 28 KB
#define TILE_ROWS 256
#define TILE_BYTES (TILE_ROWS * 128)            // 32 KB
#define SMEM_TAB_F 0
#define SMEM_BUF_F TABSZ                         // floats
#define SMEM_TOTAL ((TABSZ + 3 * TILE_ROWS * 32) * 4)   // 28KB + 96KB

__device__ float g_tab[TABSZ];

__device__ __forceinline__ unsigned smem_addr_u32(const void* p) {
    unsigned a;
    asm("{ .reg .u64 t; cvta.to.shared.u64 t, %1; cvt.u32.u64 %0, t; }"
        : "=r"(a) : "l"(p));
    return a;
}
__device__ __forceinline__ void cp16(unsigned dst, const void* src) {
    asm volatile("cp.async.cg.shared.global [%0], [%1], 16;"
                 :: "r"(dst), "l"(src));
}
#define CP_COMMIT() asm volatile("cp.async.commit_group;")
#define CP_WAIT(n)  asm volatile("cp.async.wait_group %0;" :: "n"(n))

// variables index for pair (i,j), i<j (itertools.combinations order)
__device__ __forceinline__ int pair_v(int i, int j) {
    return 32 + i * 31 - (i * (i - 1)) / 2 + (j - i - 1);
}

__global__ void KOBE_76948634075865_precompute(const float* __restrict__ vars) {
    int p = blockIdx.x, t = threadIdx.x;
    int a = t >> 4, b = t & 15;

    int A = 0, rem = p, cnt = 7;
    while (rem >= cnt) { rem -= cnt; cnt--; A++; }
    int B = A + 1 + rem;

    float sa[4], sb[4];
#pragma unroll
    for (int k = 0; k < 4; k++) {
        sa[k] = 1.0f - 2.0f * (float)((a >> k) & 1);
        sb[k] = 1.0f - 2.0f * (float)((b >> k) & 1);
    }

    float acc = 0.0f;
#pragma unroll
    for (int i2 = 0; i2 < 4; i2++)
#pragma unroll
        for (int j2 = 0; j2 < 4; j2++)
            acc += vars[pair_v(4 * A + i2, 4 * B + j2)] * sa[i2] * sb[j2];

    if (B == 7) {
#pragma unroll
        for (int i2 = 0; i2 < 4; i2++) {
            acc += vars[4 * A + i2] * sa[i2];
#pragma unroll
            for (int j2 = i2 + 1; j2 < 4; j2++)
                acc += vars[pair_v(4 * A + i2, 4 * A + j2)] * sa[i2] * sa[j2];
        }
        if (A == 6) {
#pragma unroll
            for (int i2 = 0; i2 < 4; i2++) {
                acc += vars[28 + i2] * sb[i2];
#pragma unroll
                for (int j2 = i2 + 1; j2 < 4; j2++)
                    acc += vars[pair_v(28 + i2, 28 + j2)] * sb[i2] * sb[j2];
            }
        }
    }

    g_tab[p * 256 + a * 16 + b] = acc;
}

__device__ __forceinline__ float row_energy(const float* tab, const int4* buf,
                                            int tid) {
    int sw = tid & 7;
    const int4* rp = buf + tid * 8;
    int n[8];
#pragma unroll
    for (int c = 0; c < 8; c++) {
        int4 x = rp[c ^ sw];
        n[c] = x.x + 2 * x.y + 4 * x.z + 8 * x.w;
    }
    float a0 = 0.f, a1 = 0.f, a2 = 0.f, a3 = 0.f;
    int idx = 0;
#pragma unroll
    for (int A = 0; A < 8; A++) {
#pragma unroll
        for (int B = A + 1; B < 8; B++) {
            float v = tab[idx * 256 + n[A] * 16 + n[B]];
            if ((idx & 3) == 0)      a0 += v;
            else if ((idx & 3) == 1) a1 += v;
            else if ((idx & 3) == 2) a2 += v;
            else                     a3 += v;
            idx++;
        }
    }
    return (a0 + a1) + (a2 + a3);
}

__global__ __launch_bounds__(256) void KOBE_76948634075865_eval(
    const char* __restrict__ bits, float* __restrict__ out, int batch) {
    extern __shared__ float smem[];
    unsigned sbase = smem_addr_u32(smem);
    int tid = threadIdx.x;
    const float* tab = smem;

    // group: table fill (1792 float4, 7 per thread)
#pragma unroll
    for (int k = 0; k < 7; k++) {
        int j = tid + k * 256;
        cp16(sbase + j * 16, (const char*)g_tab + j * 16);
    }
    CP_COMMIT();

    long long t0 = (long long)blockIdx.x * 4;    // first of this block's 4 tiles

    // prime tiles 0..2 into ring slots 0..2
#pragma unroll
    for (int i = 0; i < 3; i++) {
        long long r0 = (t0 + i) * TILE_ROWS;
        unsigned buf = sbase + (SMEM_BUF_F + i * TILE_ROWS * 32) * 4;
#pragma unroll
        for (int k = 0; k < 8; k++) {
            int g = k * 256 + tid;
            int r = g >> 3, c = g & 7;
            if (r0 + r < batch)
                cp16(buf + r * 128 + ((c ^ (r & 7)) << 4),
                     bits + r0 * 128 + g * 16);
        }
        CP_COMMIT();
    }

    // tile 0: wait tab + tile0 (allow 2 pending)
    CP_WAIT(2);
    __syncthreads();
    {
        const int4* buf = (const int4*)(smem + SMEM_BUF_F);
        long long row = t0 * TILE_ROWS + tid;
        if (row < batch) out[row] = row_energy(tab, buf, tid);
    }
    __syncthreads();          // everyone done reading slot 0

    // issue tile 3 into ring slot 0
    {
        long long r0 = (t0 + 3) * TILE_ROWS;
        unsigned buf = sbase + SMEM_BUF_F * 4;
#pragma unroll
        for (int k = 0; k < 8; k++) {
            int g = k * 256 + tid;
            int r = g >> 3, c = g & 7;
            if (r0 + r < batch)
                cp16(buf + r * 128 + ((c ^ (r & 7)) << 4),
                     bits + r0 * 128 + g * 16);
        }
        CP_COMMIT();
    }

    // tile 1 (slot 1): allow tiles 2,3 pending
    CP_WAIT(2);
    __syncthreads();
    {
        const int4* buf = (const int4*)(smem + SMEM_BUF_F + TILE_ROWS * 32);
        long long row = (t0 + 1) * TILE_ROWS + tid;
        if (row < batch) out[row] = row_energy(tab, buf, tid);
    }

    // tile 2 (slot 2): allow tile 3 pending
    CP_WAIT(1);
    __syncthreads();
    {
        const int4* buf = (const int4*)(smem + SMEM_BUF_F + 2 * TILE_ROWS * 32);
        long long row = (t0 + 2) * TILE_ROWS + tid;
        if (row < batch) out[row] = row_energy(tab, buf, tid);
    }

    // tile 3 (slot 0)
    CP_WAIT(0);
    __syncthreads();
    {
        const int4* buf = (const int4*)(smem + SMEM_BUF_F);
        long long row = (t0 + 3) * TILE_ROWS + tid;
        if (row < batch) out[row] = row_energy(tab, buf, tid);
    }
}

extern "C" void kernel_launch(void* const* d_in, const int* in_sizes, int n_in,
                              void* d_out, int out_size) {
    const char* bits = (const char*)d_in[0];    // [BATCH, 32] int32
    const float* vars = (const float*)d_in[1];  // [528] float32
    int batch = in_sizes[0] / 32;
    float* out = (float*)d_out;

    cudaFuncSetAttribute(KOBE_76948634075865_eval,
                         cudaFuncAttributeMaxDynamicSharedMemorySize,
                         SMEM_TOTAL);

    KOBE_76948634075865_precompute<<<NPAIRS, 256>>>(vars);

    int G = (batch + 4 * TILE_ROWS - 1) / (4 * TILE_ROWS);   // 128
    KOBE_76948634075865_eval<<<G, 256, SMEM_TOTAL>>>(bits, out, batch);
}

// round 14
// speedup vs baseline: 1.1860x; 1.1860x over previous
#include <cuda_runtime.h>
#include <cuda_bf16.h>

// Two kernels, uniform smem carveout. result(row) = sum over 28 chunk-pair
// tables T_(A,B)[nA][nB] (32 bits -> 8 nibbles; all 528 order<=2 terms folded
// into tables). Eval: 2 tiles of 256 rows per block, double-buffered cp.async
// (XOR-swizzled); grid 256 = fully co-resident (2 blocks/SM).

#define NPAIRS 28
#define TABSZ (NPAIRS * 256)                 // 7168 floats = 28 KB
#define TILE_ROWS 256
#define TILE_FLOATS (TILE_ROWS * 32)         // 8192 floats = 32 KB
#define SMEM_BUF_F TABSZ
#define SMEM_TOTAL ((TABSZ + 2 * TILE_FLOATS) * 4)   // 94208 B = 92 KB

__device__ float g_tab[TABSZ];

__device__ __forceinline__ unsigned smem_addr_u32(const void* p) {
    unsigned a;
    asm("{ .reg .u64 t; cvta.to.shared.u64 t, %1; cvt.u32.u64 %0, t; }"
        : "=r"(a) : "l"(p));
    return a;
}
__device__ __forceinline__ void cp16(unsigned dst, const void* src) {
    asm volatile("cp.async.cg.shared.global [%0], [%1], 16;"
                 :: "r"(dst), "l"(src));
}
#define CP_COMMIT() asm volatile("cp.async.commit_group;")
#define CP_WAIT(n)  asm volatile("cp.async.wait_group %0;" :: "n"(n))

// variables index for pair (i,j), i<j (itertools.combinations order)
__device__ __forceinline__ int pair_v(int i, int j) {
    return 32 + i * 31 - (i * (i - 1)) / 2 + (j - i - 1);
}

__global__ void KOBE_76948634075865_precompute(const float* __restrict__ vars) {
    extern __shared__ float dummy[];   // same dynamic smem as eval: keeps the
    (void)dummy;                       // SM carveout uniform across the graph
    int p = blockIdx.x, t = threadIdx.x;
    int a = t >> 4, b = t & 15;

    int A = 0, rem = p, cnt = 7;
    while (rem >= cnt) { rem -= cnt; cnt--; A++; }
    int B = A + 1 + rem;

    float sa[4], sb[4];
#pragma unroll
    for (int k = 0; k < 4; k++) {
        sa[k] = 1.0f - 2.0f * (float)((a >> k) & 1);
        sb[k] = 1.0f - 2.0f * (float)((b >> k) & 1);
    }

    float acc = 0.0f;
#pragma unroll
    for (int i2 = 0; i2 < 4; i2++)
#pragma unroll
        for (int j2 = 0; j2 < 4; j2++)
            acc += vars[pair_v(4 * A + i2, 4 * B + j2)] * sa[i2] * sb[j2];

    if (B == 7) {
#pragma unroll
        for (int i2 = 0; i2 < 4; i2++) {
            acc += vars[4 * A + i2] * sa[i2];
#pragma unroll
            for (int j2 = i2 + 1; j2 < 4; j2++)
                acc += vars[pair_v(4 * A + i2, 4 * A + j2)] * sa[i2] * sa[j2];
        }
        if (A == 6) {
#pragma unroll
            for (int i2 = 0; i2 < 4; i2++) {
                acc += vars[28 + i2] * sb[i2];
#pragma unroll
                for (int j2 = i2 + 1; j2 < 4; j2++)
                    acc += vars[pair_v(28 + i2, 28 + j2)] * sb[i2] * sb[j2];
            }
        }
    }

    g_tab[p * 256 + a * 16 + b] = acc;
}

__device__ __forceinline__ float row_energy(const float* tab, const int4* buf,
                                            int tid) {
    int sw = tid & 7;
    const int4* rp = buf + tid * 8;
    int n[8];
#pragma unroll
    for (int c = 0; c < 8; c++) {
        int4 x = rp[c ^ sw];
        n[c] = x.x + 2 * x.y + 4 * x.z + 8 * x.w;
    }
    float a0 = 0.f, a1 = 0.f, a2 = 0.f, a3 = 0.f;
    int idx = 0;
#pragma unroll
    for (int A = 0; A < 8; A++) {
#pragma unroll
        for (int B = A + 1; B < 8; B++) {
            float v = tab[idx * 256 + n[A] * 16 + n[B]];
            if ((idx & 3) == 0)      a0 += v;
            else if ((idx & 3) == 1) a1 += v;
            else if ((idx & 3) == 2) a2 += v;
            else                     a3 += v;
            idx++;
        }
    }
    return (a0 + a1) + (a2 + a3);
}

__device__ __forceinline__ void stage_tile(unsigned bufaddr,
                                           const char* __restrict__ bits,
                                           long long r0, int tid, int batch) {
#pragma unroll
    for (int k = 0; k < 8; k++) {
        int g = k * 256 + tid;               // 16B chunk index in tile
        int r = g >> 3, c = g & 7;
        if (r0 + r < batch)
            cp16(bufaddr + r * 128 + ((c ^ (r & 7)) << 4),
                 bits + r0 * 128 + g * 16);
    }
    CP_COMMIT();
}

__global__ __launch_bounds__(256) void KOBE_76948634075865_eval(
    const char* __restrict__ bits, float* __restrict__ out, int batch) {
    extern __shared__ float smem[];
    unsigned sbase = smem_addr_u32(smem);
    int tid = threadIdx.x;
    const float* tab = smem;

    // group 0: table fill (1792 float4, 7 per thread)
#pragma unroll
    for (int k = 0; k < 7; k++) {
        int j = tid + k * 256;
        cp16(sbase + j * 16, (const char*)g_tab + j * 16);
    }
    CP_COMMIT();

    int G = gridDim.x;
    long long tile0 = blockIdx.x;            // tiles 0..2G-1 overall
    long long tile1 = blockIdx.x + G;

    // groups 1,2: both tiles
    stage_tile(sbase + SMEM_BUF_F * 4, bits, tile0 * TILE_ROWS, tid, batch);
    stage_tile(sbase + (SMEM_BUF_F + TILE_FLOATS) * 4, bits,
               tile1 * TILE_ROWS, tid, batch);

    // tab + tile0 landed (1 group may stay pending)
    CP_WAIT(1);
    __syncthreads();
    {
        const int4* buf = (const int4*)(smem + SMEM_BUF_F);
        long long row = tile0 * TILE_ROWS + tid;
        if (row < batch) out[row] = row_energy(tab, buf, tid);
    }

    // tile1 landed
    CP_WAIT(0);
    __syncthreads();
    {
        const int4* buf = (const int4*)(smem + SMEM_BUF_F + TILE_FLOATS);
        long long row = tile1 * TILE_ROWS + tid;
        if (row < batch) out[row] = row_energy(tab, buf, tid);
    }
}

extern "C" void kernel_launch(void* const* d_in, const int* in_sizes, int n_in,
                              void* d_out, int out_size) {
    const char* bits = (const char*)d_in[0];    // [BATCH, 32] int32
    const float* vars = (const float*)d_in[1];  // [528] float32
    int batch = in_sizes[0] / 32;
    float* out = (float*)d_out;

    cudaFuncSetAttribute(KOBE_76948634075865_eval,
                         cudaFuncAttributeMaxDynamicSharedMemorySize,
                         SMEM_TOTAL);
    cudaFuncSetAttribute(KOBE_76948634075865_precompute,
                         cudaFuncAttributeMaxDynamicSharedMemorySize,
                         SMEM_TOTAL);

    // precompute launched with the SAME dynamic smem so the carveout config
    // never toggles between graph nodes / replays
    KOBE_76948634075865_precompute<<<NPAIRS, 256, SMEM_TOTAL>>>(vars);

    int G = (batch + 2 * TILE_ROWS - 1) / (2 * TILE_ROWS);   // 256
    KOBE_76948634075865_eval<<<G, 256, SMEM_TOTAL>>>(bits, out, batch);
}